// round 12
// baseline (speedup 1.0000x reference)
#include <cuda_runtime.h>
#include <cuda_bf16.h>
#include <cstdint>

// ---------------- shapes ----------------
#define NTOK 4096
#define CDIM 1024
#define NEXP 64
#define TOPK 8
#define CAP  1024
#define HS   1024
#define HE   512

// ---------------- helpers ----------------
__device__ __forceinline__ uint32_t smem_u32(const void* p) {
    uint32_t a;
    asm("{ .reg .u64 t; cvta.to.shared.u64 t, %1; cvt.u32.u64 %0, t; }" : "=r"(a) : "l"(p));
    return a;
}
#define CP_ASYNC16(dst, src) \
    asm volatile("cp.async.cg.shared.global [%0], [%1], 16;" :: "r"(dst), "l"(src))
#define CP_ASYNC4(dst, src) \
    asm volatile("cp.async.ca.shared.global [%0], [%1], 4;" :: "r"(dst), "l"(src))
#define CP_COMMIT() asm volatile("cp.async.commit_group;" ::: "memory")
#define CP_WAIT1()  asm volatile("cp.async.wait_group 1;" ::: "memory")

__device__ __forceinline__ void ldm_x4(uint32_t* r, uint32_t addr) {
    asm volatile("ldmatrix.sync.aligned.m8n8.x4.shared.b16 {%0,%1,%2,%3}, [%4];"
        : "=r"(r[0]), "=r"(r[1]), "=r"(r[2]), "=r"(r[3]) : "r"(addr));
}
#define LDS32(r, addr) \
    asm volatile("ld.shared.b32 %0, [%1];" : "=r"(r) : "r"(addr))
__device__ __forceinline__ void mma_tf32(float* d, const uint32_t* a, const uint32_t* b) {
    asm volatile(
        "mma.sync.aligned.m16n8k8.row.col.f32.tf32.tf32.f32 "
        "{%0,%1,%2,%3}, {%4,%5,%6,%7}, {%8,%9}, {%0,%1,%2,%3};"
        : "+f"(d[0]), "+f"(d[1]), "+f"(d[2]), "+f"(d[3])
        : "r"(a[0]), "r"(a[1]), "r"(a[2]), "r"(a[3]), "r"(b[0]), "r"(b[1]));
}
__device__ __forceinline__ float to_tf32(float v) {
    uint32_t r;
    asm("cvt.rna.tf32.f32 %0, %1;" : "=r"(r) : "f"(v));
    return __uint_as_float(r);
}
__device__ __forceinline__ uint32_t cvt_tf32_u(uint32_t raw) {
    uint32_t r;
    asm("cvt.rna.tf32.f32 %0, %1;" : "=r"(r) : "r"(raw));
    return r;
}

// ---------------- scratch (device globals) ----------------
__device__ float g_xr  [(size_t)NTOK * CDIM];
__device__ float g_sh  [(size_t)NTOK * HS];
__device__ float g_eh  [(size_t)NEXP * CAP * HE];
__device__ float g_eoe [(size_t)NEXP * CAP * CDIM];
__device__ int   g_counts[NEXP];
__device__ int   g_rowidx[NEXP * CAP];
__device__ int   g_slots[NTOK * TOPK];
__device__ float g_wts [NTOK * TOPK];

// ---------------- zero counts ----------------
__global__ void zero_counts_kernel(int* counts) {
    if (threadIdx.x < NEXP) counts[threadIdx.x] = 0;
}

// ---------------- router ----------------
__global__ __launch_bounds__(256) void router_kernel(
    const float* __restrict__ x, const float* __restrict__ rw, const float* __restrict__ bias,
    int* __restrict__ counts, int* __restrict__ rowidx,
    int* __restrict__ slots, float* __restrict__ wts, float* __restrict__ xr) {
    int t = blockIdx.x;
    int tid = threadIdx.x;
    __shared__ float xs[CDIM];
    __shared__ float partial[256];
    __shared__ float sc[NEXP];
    __shared__ float sb[NEXP];

    for (int i = tid; i < CDIM; i += 256) xs[i] = x[(size_t)t * CDIM + i];
    __syncthreads();

    int e = tid & 63, part = tid >> 6;
    float acc = 0.f;
    const float* rwp = rw + (size_t)(part * 256) * NEXP + e;
    #pragma unroll 8
    for (int c = 0; c < 256; c++) acc += xs[part * 256 + c] * rwp[(size_t)c * NEXP];
    partial[tid] = acc;
    __syncthreads();
    if (tid < NEXP) {
        float v = partial[tid] + partial[tid + 64] + partial[tid + 128] + partial[tid + 192];
        float s = 1.f / (1.f + __expf(-v));
        sc[tid] = s;
        sb[tid] = s + bias[tid];
    }
    __syncthreads();

    if (tid < 32) {
        float v0 = sb[tid], v1 = sb[tid + 32];
        int eid = 0;
        #pragma unroll
        for (int k = 0; k < TOPK; k++) {
            float m; int me;
            if (v0 >= v1) { m = v0; me = tid; } else { m = v1; me = tid + 32; }
            #pragma unroll
            for (int off = 16; off; off >>= 1) {
                float om = __shfl_down_sync(0xffffffffu, m, off);
                int   oe = __shfl_down_sync(0xffffffffu, me, off);
                if (om > m) { m = om; me = oe; }
            }
            me = __shfl_sync(0xffffffffu, me, 0);
            if (tid == me) v0 = -1e30f;
            if (tid == me - 32) v1 = -1e30f;
            if (tid == k) eid = me;
        }
        float sv = (tid < TOPK) ? sc[eid] : 0.f;
        float ws = sv;
        #pragma unroll
        for (int off = 4; off; off >>= 1) ws += __shfl_down_sync(0xffffffffu, ws, off, 8);
        ws = __shfl_sync(0xffffffffu, ws, 0);
        if (tid < TOPK) {
            int pos  = atomicAdd(&counts[eid], 1);
            int slot = eid * CAP + pos;
            rowidx[slot] = t;
            slots[t * TOPK + tid] = slot;
            wts  [t * TOPK + tid] = sv / ws;
        }
    }

    for (int i = tid; i < CDIM; i += 256)
        xr[(size_t)t * CDIM + i] = to_tf32(xs[i]);
}

// ---------------- tf32 mma.sync GEMM, transposeless B ----------------
// D[M,N] = A[M,K] (row-major, tf32-rounded) @ B[K,N] (native weights, rounded in-reg).
// CTA tile 128x128, 8 warps of 64x32, Kc=32, 3-stage ring, 2 CTAs/SM.
// Stage: A 128x(36 fl pad -> 144B) = 18432 B; B 32 k-rows x 136 fl pad (544B) = 17408 B.
#define ROWB 144
#define BROW 544
#define A_BYTES 18432
#define STG_BYTES 35840

// gOff == 0: plain cols n0+c.  gOff > 0: (y,g) interleave — local col c maps to
// gmem col (c even: n0/2 + c/2 ; c odd: gOff + n0/2 + c/2).
__device__ __forceinline__ void issue_stage(
    uint32_t sdst, const float* __restrict__ pA, const float* __restrict__ pB,
    int K, int N, int kcol, int n0, int gOff, int tid, const int* ar) {
    #pragma unroll
    for (int i = 0; i < 4; i++) {
        int id = tid + 256 * i;
        int row = id >> 3, c16 = id & 7;
        uint32_t so = (uint32_t)(row * ROWB + c16 * 16);
        CP_ASYNC16(sdst + so, pA + (size_t)ar[i] * K + kcol + c16 * 4);
    }
    int cb = n0 >> 1;
    #pragma unroll
    for (int i = 0; i < 16; i++) {
        int id = tid + 256 * i;
        int kr = id >> 7, c = id & 127;
        int col = gOff ? ((c & 1) ? (gOff + cb + (c >> 1)) : (cb + (c >> 1))) : (n0 + c);
        CP_ASYNC4(sdst + A_BYTES + (uint32_t)(kr * BROW + c * 4),
                  pB + (size_t)(kcol + kr) * N + col);
    }
}

__global__ __launch_bounds__(256, 2) void gemm_kernel(
    const float* __restrict__ A, const float* __restrict__ B,
    float* __restrict__ D, float* __restrict__ H,
    int M, int N, int K, int gOff,
    long sAz, long sBz, long sDz,
    const int* __restrict__ counts, const int* __restrict__ rowidx) {
    extern __shared__ __align__(128) char smem[];
    int z = blockIdx.z;
    if (counts) M = counts[z];
    int m0 = blockIdx.y * 128;
    if (m0 >= M) return;
    int n0 = blockIdx.x * 128;
    A += (size_t)z * sAz; B += (size_t)z * sBz;

    int tid = threadIdx.x, wid = tid >> 5, lane = tid & 31;
    int wm = (wid & 1) * 64;
    int wn = (wid >> 1) * 32;
    uint32_t sbase = smem_u32(smem);

    const float* pA;
    int ar[4];
    if (rowidx) {
        const int* ridx = rowidx + (size_t)z * CAP + m0;
        pA = A;
        #pragma unroll
        for (int i = 0; i < 4; i++) ar[i] = ridx[(tid >> 3) + 32 * i];
    } else {
        pA = A + (size_t)m0 * K;
        #pragma unroll
        for (int i = 0; i < 4; i++) ar[i] = (tid >> 3) + 32 * i;
    }

    float acc[4][4][4];
    #pragma unroll
    for (int i = 0; i < 4; i++)
        #pragma unroll
        for (int j = 0; j < 4; j++)
            #pragma unroll
            for (int r = 0; r < 4; r++) acc[i][j][r] = 0.f;

    const int nk = K >> 5;
    issue_stage(sbase,             pA, B, K, N, 0,  n0, gOff, tid, ar); CP_COMMIT();
    issue_stage(sbase + STG_BYTES, pA, B, K, N, 32, n0, gOff, tid, ar); CP_COMMIT();

    // A ldmatrix per-lane offset (bytes)
    uint32_t aoff = (uint32_t)((wm + (lane & 15)) * ROWB + ((lane >> 4) & 1) * 16);
    // B LDS per-lane offsets (bytes): rows k=lane%4 (+4), col wn + lane/4
    uint32_t brow0 = (uint32_t)((lane & 3) * BROW);
    uint32_t bcol  = (uint32_t)((wn + (lane >> 2)) * 4);

    int stg = 0;
    for (int kc = 0; kc < nk; kc++) {
        CP_WAIT1();
        __syncthreads();
        if (kc + 2 < nk) {
            int nx = stg + 2; if (nx >= 3) nx -= 3;
            issue_stage(sbase + nx * STG_BYTES, pA, B, K, N, (kc + 2) * 32, n0, gOff, tid, ar);
        }
        CP_COMMIT();

        uint32_t sA = sbase + stg * STG_BYTES;
        uint32_t sB = sA + A_BYTES + brow0 + bcol;
        #pragma unroll
        for (int s = 0; s < 4; s++) {
            uint32_t a[4][4];
            #pragma unroll
            for (int mi = 0; mi < 4; mi++)
                ldm_x4(a[mi], sA + aoff + (uint32_t)(mi * 16 * ROWB + s * 32));
            #pragma unroll
            for (int g = 0; g < 4; g++) {
                uint32_t b[2];
                LDS32(b[0], sB + (uint32_t)(s * 8 * BROW + g * 32));
                LDS32(b[1], sB + (uint32_t)(s * 8 * BROW + 4 * BROW + g * 32));
                b[0] = cvt_tf32_u(b[0]);
                b[1] = cvt_tf32_u(b[1]);
                #pragma unroll
                for (int mi = 0; mi < 4; mi++)
                    mma_tf32(acc[mi][g], a[mi], b);
            }
        }
        if (++stg == 3) stg = 0;
    }

    int r0 = lane >> 2, c0 = (lane & 3) * 2;
    if (H) {
        // fused SwiGLU: local cols (y,g) interleaved -> h = silu(g)*y, tf32-rounded
        int halfN = N >> 1;
        H += (size_t)z * sDz;
        #pragma unroll
        for (int mi = 0; mi < 4; mi++) {
            #pragma unroll
            for (int ni = 0; ni < 4; ni++) {
                int row = m0 + wm + mi * 16 + r0;
                int p = (n0 + wn + ni * 8 + c0) >> 1;
                float y0 = acc[mi][ni][0], gg0 = acc[mi][ni][1];
                float y1 = acc[mi][ni][2], gg1 = acc[mi][ni][3];
                H[(size_t)row * halfN + p]       = to_tf32(y0 * gg0 / (1.f + __expf(-gg0)));
                H[(size_t)(row + 8) * halfN + p] = to_tf32(y1 * gg1 / (1.f + __expf(-gg1)));
            }
        }
    } else {
        D += (size_t)z * sDz;
        #pragma unroll
        for (int mi = 0; mi < 4; mi++) {
            #pragma unroll
            for (int ni = 0; ni < 4; ni++) {
                int row = m0 + wm + mi * 16 + r0;
                int col = n0 + wn + ni * 8 + c0;
                *(float2*)(D + (size_t)row * N + col) = make_float2(acc[mi][ni][0], acc[mi][ni][1]);
                *(float2*)(D + (size_t)(row + 8) * N + col) = make_float2(acc[mi][ni][2], acc[mi][ni][3]);
            }
        }
    }
}

// ---------------- combine ----------------
__global__ __launch_bounds__(256) void combine_kernel(
    const float* __restrict__ oe, const int* __restrict__ slots,
    const float* __restrict__ wts, float* __restrict__ out) {
    int t = blockIdx.x;
    int c = threadIdx.x * 4;
    int sl[TOPK]; float ww[TOPK];
    #pragma unroll
    for (int k = 0; k < TOPK; k++) { sl[k] = slots[t * TOPK + k]; ww[k] = wts[t * TOPK + k]; }
    float4 acc = *(float4*)(out + (size_t)t * CDIM + c);
    #pragma unroll
    for (int k = 0; k < TOPK; k++) {
        float4 v = *(const float4*)(oe + (size_t)sl[k] * CDIM + c);
        acc.x += ww[k] * v.x; acc.y += ww[k] * v.y;
        acc.z += ww[k] * v.z; acc.w += ww[k] * v.w;
    }
    *(float4*)(out + (size_t)t * CDIM + c) = acc;
}

// ---------------- launch (two-stream DAG, graph-capturable fork/join) ----------------
extern "C" void kernel_launch(void* const* d_in, const int* in_sizes, int n_in,
                              void* d_out, int out_size) {
    const float* x       = (const float*)d_in[0];
    const float* rw      = (const float*)d_in[1];
    const float* bias    = (const float*)d_in[2];
    const float* sup_w   = (const float*)d_in[3];
    const float* sdown_w = (const float*)d_in[4];
    const float* eup_w   = (const float*)d_in[5];
    const float* edown_w = (const float*)d_in[6];
    float* out = (float*)d_out;
    (void)in_sizes; (void)n_in; (void)out_size;

    float *xr, *sh, *eh, *eoe, *wts;
    int *counts, *rowidx, *slots;
    cudaGetSymbolAddress((void**)&xr, g_xr);
    cudaGetSymbolAddress((void**)&sh, g_sh);
    cudaGetSymbolAddress((void**)&eh, g_eh);
    cudaGetSymbolAddress((void**)&eoe, g_eoe);
    cudaGetSymbolAddress((void**)&counts, g_counts);
    cudaGetSymbolAddress((void**)&rowidx, g_rowidx);
    cudaGetSymbolAddress((void**)&slots, g_slots);
    cudaGetSymbolAddress((void**)&wts, g_wts);

    cudaFuncSetAttribute(gemm_kernel, cudaFuncAttributeMaxDynamicSharedMemorySize, 3 * STG_BYTES);
    const int gsmem = 3 * STG_BYTES;

    static cudaStream_t s1 = nullptr;
    static cudaEvent_t evFork = nullptr, evJoin = nullptr;
    if (!s1) {
        cudaStreamCreateWithFlags(&s1, cudaStreamNonBlocking);
        cudaEventCreateWithFlags(&evFork, cudaEventDisableTiming);
        cudaEventCreateWithFlags(&evJoin, cudaEventDisableTiming);
    }

    // 1. routing (main stream)
    zero_counts_kernel<<<1, 64>>>(counts);
    router_kernel<<<NTOK, 256>>>(x, rw, bias, counts, rowidx, slots, wts, xr);

    // ---- fork: expert chain on main, shared chain on s1 ----
    cudaEventRecord(evFork, 0);
    cudaStreamWaitEvent(s1, evFork, 0);

    // main: expert-up (gather + fused swiglu, interleaved B) -> expert-down
    gemm_kernel<<<dim3(2 * HE / 128, CAP / 128, NEXP), 256, gsmem>>>(
        xr, eup_w, nullptr, eh, CAP, 2 * HE, CDIM, HE,
        0, (long)CDIM * (2 * HE), (long)CAP * HE, counts, rowidx);
    gemm_kernel<<<dim3(CDIM / 128, CAP / 128, NEXP), 256, gsmem>>>(
        eh, edown_w, eoe, nullptr, CAP, CDIM, HE, 0,
        (long)CAP * HE, (long)HE * CDIM, (long)CAP * CDIM, counts, nullptr);

    // s1: shared-up -> shared-down (writes out)
    gemm_kernel<<<dim3(2 * HS / 128, NTOK / 128, 1), 256, gsmem, s1>>>(
        xr, sup_w, nullptr, sh, NTOK, 2 * HS, CDIM, HS, 0, 0, 0, nullptr, nullptr);
    gemm_kernel<<<dim3(CDIM / 128, NTOK / 128, 1), 256, gsmem, s1>>>(
        sh, sdown_w, out, nullptr, NTOK, CDIM, HS, 0, 0, 0, 0, nullptr, nullptr);

    // ---- join, then combine ----
    cudaEventRecord(evJoin, s1);
    cudaStreamWaitEvent(0, evJoin, 0);

    combine_kernel<<<NTOK, 256>>>(eoe, slots, wts, out);
}

// round 13
// speedup vs baseline: 1.0898x; 1.0898x over previous
#include <cuda_runtime.h>
#include <cuda_bf16.h>
#include <cstdint>

// ---------------- shapes ----------------
#define NTOK 4096
#define CDIM 1024
#define NEXP 64
#define TOPK 8
#define CAP  1024
#define HS   1024
#define HE   512

// ---------------- helpers ----------------
__device__ __forceinline__ uint32_t smem_u32(const void* p) {
    uint32_t a;
    asm("{ .reg .u64 t; cvta.to.shared.u64 t, %1; cvt.u32.u64 %0, t; }" : "=r"(a) : "l"(p));
    return a;
}
#define CP_ASYNC16(dst, src) \
    asm volatile("cp.async.cg.shared.global [%0], [%1], 16;" :: "r"(dst), "l"(src))
#define CP_COMMIT() asm volatile("cp.async.commit_group;" ::: "memory")
#define CP_WAIT1()  asm volatile("cp.async.wait_group 1;" ::: "memory")

__device__ __forceinline__ void ldm_x4(uint32_t* r, uint32_t addr) {
    asm volatile("ldmatrix.sync.aligned.m8n8.x4.shared.b16 {%0,%1,%2,%3}, [%4];"
        : "=r"(r[0]), "=r"(r[1]), "=r"(r[2]), "=r"(r[3]) : "r"(addr));
}
#define LDS32(r, addr) \
    asm volatile("ld.shared.b32 %0, [%1];" : "=r"(r) : "r"(addr))
__device__ __forceinline__ void mma_tf32(float* d, const uint32_t* a, const uint32_t* b) {
    asm volatile(
        "mma.sync.aligned.m16n8k8.row.col.f32.tf32.tf32.f32 "
        "{%0,%1,%2,%3}, {%4,%5,%6,%7}, {%8,%9}, {%0,%1,%2,%3};"
        : "+f"(d[0]), "+f"(d[1]), "+f"(d[2]), "+f"(d[3])
        : "r"(a[0]), "r"(a[1]), "r"(a[2]), "r"(a[3]), "r"(b[0]), "r"(b[1]));
}
__device__ __forceinline__ float to_tf32(float v) {
    uint32_t r;
    asm("cvt.rna.tf32.f32 %0, %1;" : "=r"(r) : "f"(v));
    return __uint_as_float(r);
}
__device__ __forceinline__ uint32_t cvt_tf32_u(uint32_t raw) {
    uint32_t r;
    asm("cvt.rna.tf32.f32 %0, %1;" : "=r"(r) : "r"(raw));
    return r;
}

// ---------------- scratch (device globals) ----------------
__device__ float g_xr  [(size_t)NTOK * CDIM];
__device__ float g_sh  [(size_t)NTOK * HS];
__device__ float g_eh  [(size_t)NEXP * CAP * HE];
__device__ float g_eoe [(size_t)NEXP * CAP * CDIM];
__device__ int   g_counts[NEXP];
__device__ int   g_rowidx[NEXP * CAP];
__device__ int   g_slots[NTOK * TOPK];
__device__ float g_wts [NTOK * TOPK];

// ---------------- zero counts ----------------
__global__ void zero_counts_kernel(int* counts) {
    if (threadIdx.x < NEXP) counts[threadIdx.x] = 0;
}

// ---------------- router ----------------
__global__ __launch_bounds__(256) void router_kernel(
    const float* __restrict__ x, const float* __restrict__ rw, const float* __restrict__ bias,
    int* __restrict__ counts, int* __restrict__ rowidx,
    int* __restrict__ slots, float* __restrict__ wts, float* __restrict__ xr) {
    int t = blockIdx.x;
    int tid = threadIdx.x;
    __shared__ float xs[CDIM];
    __shared__ float partial[256];
    __shared__ float sc[NEXP];
    __shared__ float sb[NEXP];

    for (int i = tid; i < CDIM; i += 256) xs[i] = x[(size_t)t * CDIM + i];
    __syncthreads();

    int e = tid & 63, part = tid >> 6;
    float acc = 0.f;
    const float* rwp = rw + (size_t)(part * 256) * NEXP + e;
    #pragma unroll 8
    for (int c = 0; c < 256; c++) acc += xs[part * 256 + c] * rwp[(size_t)c * NEXP];
    partial[tid] = acc;
    __syncthreads();
    if (tid < NEXP) {
        float v = partial[tid] + partial[tid + 64] + partial[tid + 128] + partial[tid + 192];
        float s = 1.f / (1.f + __expf(-v));
        sc[tid] = s;
        sb[tid] = s + bias[tid];
    }
    __syncthreads();

    if (tid < 32) {
        float v0 = sb[tid], v1 = sb[tid + 32];
        int eid = 0;
        #pragma unroll
        for (int k = 0; k < TOPK; k++) {
            float m; int me;
            if (v0 >= v1) { m = v0; me = tid; } else { m = v1; me = tid + 32; }
            #pragma unroll
            for (int off = 16; off; off >>= 1) {
                float om = __shfl_down_sync(0xffffffffu, m, off);
                int   oe = __shfl_down_sync(0xffffffffu, me, off);
                if (om > m) { m = om; me = oe; }
            }
            me = __shfl_sync(0xffffffffu, me, 0);
            if (tid == me) v0 = -1e30f;
            if (tid == me - 32) v1 = -1e30f;
            if (tid == k) eid = me;
        }
        float sv = (tid < TOPK) ? sc[eid] : 0.f;
        float ws = sv;
        #pragma unroll
        for (int off = 4; off; off >>= 1) ws += __shfl_down_sync(0xffffffffu, ws, off, 8);
        ws = __shfl_sync(0xffffffffu, ws, 0);
        if (tid < TOPK) {
            int pos  = atomicAdd(&counts[eid], 1);
            int slot = eid * CAP + pos;
            rowidx[slot] = t;
            slots[t * TOPK + tid] = slot;
            wts  [t * TOPK + tid] = sv / ws;
        }
    }

    for (int i = tid; i < CDIM; i += 256)
        xr[(size_t)t * CDIM + i] = to_tf32(xs[i]);
}

// ---------------- tf32 mma.sync GEMM, transposeless B (16B fills) ----------------
// D[M,N] = A[M,K] (row-major, tf32) @ B[K,N] (native weights, tf32-rounded in-reg).
// CTA tile 128x128B-cols, 8 warps, Kc=32, 3-stage ring, 2 CTAs/SM.
// Up-GEMMs (gOff>0): smem B cols 0..63 = y half [hb..hb+64), 64..127 = g half
// [gOff+hb..). Warp fragments: groups 0,1 = y, groups 2,3 = matching g.
#define ROWB 144
#define BROW 544
#define A_BYTES 18432
#define STG_BYTES 35840

__device__ __forceinline__ void issue_stage(
    uint32_t sdst, const float* __restrict__ pA, const float* __restrict__ pB,
    int K, int N, int kcol, int n0, int gOff, int tid, const int* ar) {
    #pragma unroll
    for (int i = 0; i < 4; i++) {
        int id = tid + 256 * i;
        int row = id >> 3, c16 = id & 7;
        uint32_t so = (uint32_t)(row * ROWB + c16 * 16);
        CP_ASYNC16(sdst + so, pA + (size_t)ar[i] * K + kcol + c16 * 4);
    }
    int hb = n0 >> 1;
    #pragma unroll
    for (int i = 0; i < 4; i++) {
        int id = tid + 256 * i;
        int kr = id >> 5, ch = id & 31;       // k-row, 16B chunk (4 cols)
        int col;
        if (gOff) col = (ch < 16) ? (hb + ch * 4) : (gOff + hb + (ch - 16) * 4);
        else      col = n0 + ch * 4;
        CP_ASYNC16(sdst + A_BYTES + (uint32_t)(kr * BROW + ch * 16),
                   pB + (size_t)(kcol + kr) * N + col);
    }
}

__global__ __launch_bounds__(256, 2) void gemm_kernel(
    const float* __restrict__ A, const float* __restrict__ B,
    float* __restrict__ D, float* __restrict__ H,
    int M, int N, int K, int gOff,
    long sAz, long sBz, long sDz,
    const int* __restrict__ counts, const int* __restrict__ rowidx) {
    extern __shared__ __align__(128) char smem[];
    int z = blockIdx.z;
    if (counts) M = counts[z];
    int m0 = blockIdx.y * 128;
    if (m0 >= M) return;
    int n0 = blockIdx.x * 128;
    A += (size_t)z * sAz; B += (size_t)z * sBz;

    int tid = threadIdx.x, wid = tid >> 5, lane = tid & 31;
    int wm = (wid & 1) * 64;
    uint32_t sbase = smem_u32(smem);

    const float* pA;
    int ar[4];
    if (rowidx) {
        const int* ridx = rowidx + (size_t)z * CAP + m0;
        pA = A;
        #pragma unroll
        for (int i = 0; i < 4; i++) ar[i] = ridx[(tid >> 3) + 32 * i];
    } else {
        pA = A + (size_t)m0 * K;
        #pragma unroll
        for (int i = 0; i < 4; i++) ar[i] = (tid >> 3) + 32 * i;
    }

    float acc[4][4][4];
    #pragma unroll
    for (int i = 0; i < 4; i++)
        #pragma unroll
        for (int j = 0; j < 4; j++)
            #pragma unroll
            for (int r = 0; r < 4; r++) acc[i][j][r] = 0.f;

    const int nk = K >> 5;
    issue_stage(sbase,             pA, B, K, N, 0,  n0, gOff, tid, ar); CP_COMMIT();
    issue_stage(sbase + STG_BYTES, pA, B, K, N, 32, n0, gOff, tid, ar); CP_COMMIT();

    // A ldmatrix per-lane offset (bytes)
    uint32_t aoff = (uint32_t)((wm + (lane & 15)) * ROWB + ((lane >> 4) & 1) * 16);
    // B per-group smem col bases
    int sbg[4];
    if (gOff) {
        int wny = (wid >> 1) * 16;
        #pragma unroll
        for (int g = 0; g < 4; g++) sbg[g] = ((g & 2) ? 64 : 0) + wny + (g & 1) * 8;
    } else {
        int wn = (wid >> 1) * 32;
        #pragma unroll
        for (int g = 0; g < 4; g++) sbg[g] = wn + g * 8;
    }
    uint32_t brow0 = (uint32_t)((lane & 3) * BROW);
    uint32_t blane = (uint32_t)((lane >> 2) * 4);

    int stg = 0;
    for (int kc = 0; kc < nk; kc++) {
        CP_WAIT1();
        __syncthreads();
        if (kc + 2 < nk) {
            int nx = stg + 2; if (nx >= 3) nx -= 3;
            issue_stage(sbase + nx * STG_BYTES, pA, B, K, N, (kc + 2) * 32, n0, gOff, tid, ar);
        }
        CP_COMMIT();

        uint32_t sA = sbase + stg * STG_BYTES;
        uint32_t sB = sA + A_BYTES + brow0 + blane;
        #pragma unroll
        for (int s = 0; s < 4; s++) {
            uint32_t a[4][4];
            #pragma unroll
            for (int mi = 0; mi < 4; mi++)
                ldm_x4(a[mi], sA + aoff + (uint32_t)(mi * 16 * ROWB + s * 32));
            #pragma unroll
            for (int g = 0; g < 4; g++) {
                uint32_t b[2];
                uint32_t ba = sB + (uint32_t)(s * 8 * BROW + sbg[g] * 4);
                LDS32(b[0], ba);
                LDS32(b[1], ba + 4 * BROW);
                b[0] = cvt_tf32_u(b[0]);
                b[1] = cvt_tf32_u(b[1]);
                #pragma unroll
                for (int mi = 0; mi < 4; mi++)
                    mma_tf32(acc[mi][g], a[mi], b);
            }
        }
        if (++stg == 3) stg = 0;
    }

    int r0 = lane >> 2, c0 = (lane & 3) * 2;
    if (H) {
        // fused SwiGLU: y = groups 0,1 ; gate = groups 2,3 (same register slots)
        int halfN = N >> 1;
        int hb = n0 >> 1;
        int wny = (wid >> 1) * 16;
        H += (size_t)z * sDz;
        #pragma unroll
        for (int mi = 0; mi < 4; mi++) {
            #pragma unroll
            for (int g = 0; g < 2; g++) {
                int row = m0 + wm + mi * 16 + r0;
                int hcol = hb + wny + g * 8 + c0;
                float y0 = acc[mi][g][0], gg0 = acc[mi][g + 2][0];
                float y1 = acc[mi][g][1], gg1 = acc[mi][g + 2][1];
                float y2 = acc[mi][g][2], gg2 = acc[mi][g + 2][2];
                float y3 = acc[mi][g][3], gg3 = acc[mi][g + 2][3];
                H[(size_t)row * halfN + hcol]           = to_tf32(y0 * gg0 / (1.f + __expf(-gg0)));
                H[(size_t)row * halfN + hcol + 1]       = to_tf32(y1 * gg1 / (1.f + __expf(-gg1)));
                H[(size_t)(row + 8) * halfN + hcol]     = to_tf32(y2 * gg2 / (1.f + __expf(-gg2)));
                H[(size_t)(row + 8) * halfN + hcol + 1] = to_tf32(y3 * gg3 / (1.f + __expf(-gg3)));
            }
        }
    } else {
        D += (size_t)z * sDz;
        int wn = (wid >> 1) * 32;
        #pragma unroll
        for (int mi = 0; mi < 4; mi++) {
            #pragma unroll
            for (int g = 0; g < 4; g++) {
                int row = m0 + wm + mi * 16 + r0;
                int col = n0 + wn + g * 8 + c0;
                *(float2*)(D + (size_t)row * N + col) = make_float2(acc[mi][g][0], acc[mi][g][1]);
                *(float2*)(D + (size_t)(row + 8) * N + col) = make_float2(acc[mi][g][2], acc[mi][g][3]);
            }
        }
    }
}

// ---------------- combine ----------------
__global__ __launch_bounds__(256) void combine_kernel(
    const float* __restrict__ oe, const int* __restrict__ slots,
    const float* __restrict__ wts, float* __restrict__ out) {
    int t = blockIdx.x;
    int c = threadIdx.x * 4;
    int sl[TOPK]; float ww[TOPK];
    #pragma unroll
    for (int k = 0; k < TOPK; k++) { sl[k] = slots[t * TOPK + k]; ww[k] = wts[t * TOPK + k]; }
    float4 acc = *(float4*)(out + (size_t)t * CDIM + c);
    #pragma unroll
    for (int k = 0; k < TOPK; k++) {
        float4 v = *(const float4*)(oe + (size_t)sl[k] * CDIM + c);
        acc.x += ww[k] * v.x; acc.y += ww[k] * v.y;
        acc.z += ww[k] * v.z; acc.w += ww[k] * v.w;
    }
    *(float4*)(out + (size_t)t * CDIM + c) = acc;
}

// ---------------- launch (two-stream DAG, graph-capturable fork/join) ----------------
extern "C" void kernel_launch(void* const* d_in, const int* in_sizes, int n_in,
                              void* d_out, int out_size) {
    const float* x       = (const float*)d_in[0];
    const float* rw      = (const float*)d_in[1];
    const float* bias    = (const float*)d_in[2];
    const float* sup_w   = (const float*)d_in[3];
    const float* sdown_w = (const float*)d_in[4];
    const float* eup_w   = (const float*)d_in[5];
    const float* edown_w = (const float*)d_in[6];
    float* out = (float*)d_out;
    (void)in_sizes; (void)n_in; (void)out_size;

    float *xr, *sh, *eh, *eoe, *wts;
    int *counts, *rowidx, *slots;
    cudaGetSymbolAddress((void**)&xr, g_xr);
    cudaGetSymbolAddress((void**)&sh, g_sh);
    cudaGetSymbolAddress((void**)&eh, g_eh);
    cudaGetSymbolAddress((void**)&eoe, g_eoe);
    cudaGetSymbolAddress((void**)&counts, g_counts);
    cudaGetSymbolAddress((void**)&rowidx, g_rowidx);
    cudaGetSymbolAddress((void**)&slots, g_slots);
    cudaGetSymbolAddress((void**)&wts, g_wts);

    cudaFuncSetAttribute(gemm_kernel, cudaFuncAttributeMaxDynamicSharedMemorySize, 3 * STG_BYTES);
    const int gsmem = 3 * STG_BYTES;

    static cudaStream_t s1 = nullptr;
    static cudaEvent_t evFork = nullptr, evJoin = nullptr;
    if (!s1) {
        cudaStreamCreateWithFlags(&s1, cudaStreamNonBlocking);
        cudaEventCreateWithFlags(&evFork, cudaEventDisableTiming);
        cudaEventCreateWithFlags(&evJoin, cudaEventDisableTiming);
    }

    // 1. routing (main stream)
    zero_counts_kernel<<<1, 64>>>(counts);
    router_kernel<<<NTOK, 256>>>(x, rw, bias, counts, rowidx, slots, wts, xr);

    // ---- fork: expert chain on main, shared chain on s1 ----
    cudaEventRecord(evFork, 0);
    cudaStreamWaitEvent(s1, evFork, 0);

    // main: expert-up (gather + fused swiglu, split-half B) -> expert-down
    gemm_kernel<<<dim3(2 * HE / 128, CAP / 128, NEXP), 256, gsmem>>>(
        xr, eup_w, nullptr, eh, CAP, 2 * HE, CDIM, HE,
        0, (long)CDIM * (2 * HE), (long)CAP * HE, counts, rowidx);
    gemm_kernel<<<dim3(CDIM / 128, CAP / 128, NEXP), 256, gsmem>>>(
        eh, edown_w, eoe, nullptr, CAP, CDIM, HE, 0,
        (long)CAP * HE, (long)HE * CDIM, (long)CAP * CDIM, counts, nullptr);

    // s1: shared-up -> shared-down (writes out)
    gemm_kernel<<<dim3(2 * HS / 128, NTOK / 128, 1), 256, gsmem, s1>>>(
        xr, sup_w, nullptr, sh, NTOK, 2 * HS, CDIM, HS, 0, 0, 0, nullptr, nullptr);
    gemm_kernel<<<dim3(CDIM / 128, NTOK / 128, 1), 256, gsmem, s1>>>(
        sh, sdown_w, out, nullptr, NTOK, CDIM, HS, 0, 0, 0, 0, nullptr, nullptr);

    // ---- join, then combine ----
    cudaEventRecord(evJoin, s1);
    cudaStreamWaitEvent(0, evJoin, 0);

    combine_kernel<<<NTOK, 256>>>(eoe, slots, wts, out);
}

// round 14
// speedup vs baseline: 1.1519x; 1.0570x over previous
#include <cuda_runtime.h>
#include <cuda_bf16.h>
#include <cstdint>

// ---------------- shapes ----------------
#define NTOK 4096
#define CDIM 1024
#define NEXP 64
#define TOPK 8
#define CAP  1024
#define HS   1024
#define HE   512

// ---------------- helpers ----------------
__device__ __forceinline__ uint32_t smem_u32(const void* p) {
    uint32_t a;
    asm("{ .reg .u64 t; cvta.to.shared.u64 t, %1; cvt.u32.u64 %0, t; }" : "=r"(a) : "l"(p));
    return a;
}
#define CP_ASYNC16(dst, src) \
    asm volatile("cp.async.cg.shared.global [%0], [%1], 16;" :: "r"(dst), "l"(src))
#define CP_COMMIT() asm volatile("cp.async.commit_group;" ::: "memory")
#define CP_WAIT1()  asm volatile("cp.async.wait_group 1;" ::: "memory")

__device__ __forceinline__ void ldm_x4(uint32_t* r, uint32_t addr) {
    asm volatile("ldmatrix.sync.aligned.m8n8.x4.shared.b16 {%0,%1,%2,%3}, [%4];"
        : "=r"(r[0]), "=r"(r[1]), "=r"(r[2]), "=r"(r[3]) : "r"(addr));
}
#define LDS32(r, addr) \
    asm volatile("ld.shared.b32 %0, [%1];" : "=r"(r) : "r"(addr))
__device__ __forceinline__ void mma_tf32(float* d, const uint32_t* a, const uint32_t* b) {
    asm volatile(
        "mma.sync.aligned.m16n8k8.row.col.f32.tf32.tf32.f32 "
        "{%0,%1,%2,%3}, {%4,%5,%6,%7}, {%8,%9}, {%0,%1,%2,%3};"
        : "+f"(d[0]), "+f"(d[1]), "+f"(d[2]), "+f"(d[3])
        : "r"(a[0]), "r"(a[1]), "r"(a[2]), "r"(a[3]), "r"(b[0]), "r"(b[1]));
}
__device__ __forceinline__ float to_tf32(float v) {
    uint32_t r;
    asm("cvt.rna.tf32.f32 %0, %1;" : "=r"(r) : "f"(v));
    return __uint_as_float(r);
}
__device__ __forceinline__ uint32_t cvt_tf32_u(uint32_t raw) {
    uint32_t r;
    asm("cvt.rna.tf32.f32 %0, %1;" : "=r"(r) : "r"(raw));
    return r;
}

// ---------------- scratch (device globals) ----------------
__device__ float g_xr  [(size_t)NTOK * CDIM];
__device__ float g_sh  [(size_t)NTOK * HS];
__device__ float g_eh  [(size_t)NEXP * CAP * HE];
__device__ int   g_counts[NEXP];
__device__ int   g_rowidx[NEXP * CAP];
__device__ float g_swts [NEXP * CAP];

// ---------------- zero counts ----------------
__global__ void zero_counts_kernel(int* counts) {
    if (threadIdx.x < NEXP) counts[threadIdx.x] = 0;
}

// ---------------- xr: tf32-round x ----------------
__global__ void xr_kernel(const float* __restrict__ x, float* __restrict__ xr) {
    size_t i4 = (size_t)blockIdx.x * blockDim.x + threadIdx.x;
    if (i4 >= (size_t)NTOK * CDIM / 4) return;
    float4 v = *(const float4*)(x + i4 * 4);
    v.x = to_tf32(v.x); v.y = to_tf32(v.y);
    v.z = to_tf32(v.z); v.w = to_tf32(v.w);
    *(float4*)(xr + i4 * 4) = v;
}

// ---------------- router: scores, warp top-8, slot assign (rowidx + swts) ----------------
__global__ __launch_bounds__(256) void router_kernel(
    const float* __restrict__ x, const float* __restrict__ rw, const float* __restrict__ bias,
    int* __restrict__ counts, int* __restrict__ rowidx, float* __restrict__ swts) {
    int t = blockIdx.x;
    int tid = threadIdx.x;
    __shared__ float xs[CDIM];
    __shared__ float partial[256];
    __shared__ float sc[NEXP];
    __shared__ float sb[NEXP];

    for (int i = tid; i < CDIM; i += 256) xs[i] = x[(size_t)t * CDIM + i];
    __syncthreads();

    int e = tid & 63, part = tid >> 6;
    float acc = 0.f;
    const float* rwp = rw + (size_t)(part * 256) * NEXP + e;
    #pragma unroll 8
    for (int c = 0; c < 256; c++) acc += xs[part * 256 + c] * rwp[(size_t)c * NEXP];
    partial[tid] = acc;
    __syncthreads();
    if (tid < NEXP) {
        float v = partial[tid] + partial[tid + 64] + partial[tid + 128] + partial[tid + 192];
        float s = 1.f / (1.f + __expf(-v));
        sc[tid] = s;
        sb[tid] = s + bias[tid];
    }
    __syncthreads();

    if (tid < 32) {
        float v0 = sb[tid], v1 = sb[tid + 32];
        int eid = 0;
        #pragma unroll
        for (int k = 0; k < TOPK; k++) {
            float m; int me;
            if (v0 >= v1) { m = v0; me = tid; } else { m = v1; me = tid + 32; }
            #pragma unroll
            for (int off = 16; off; off >>= 1) {
                float om = __shfl_down_sync(0xffffffffu, m, off);
                int   oe = __shfl_down_sync(0xffffffffu, me, off);
                if (om > m) { m = om; me = oe; }
            }
            me = __shfl_sync(0xffffffffu, me, 0);
            if (tid == me) v0 = -1e30f;
            if (tid == me - 32) v1 = -1e30f;
            if (tid == k) eid = me;
        }
        float sv = (tid < TOPK) ? sc[eid] : 0.f;
        float ws = sv;
        #pragma unroll
        for (int off = 4; off; off >>= 1) ws += __shfl_down_sync(0xffffffffu, ws, off, 8);
        ws = __shfl_sync(0xffffffffu, ws, 0);
        if (tid < TOPK) {
            int pos  = atomicAdd(&counts[eid], 1);
            int slot = eid * CAP + pos;
            rowidx[slot] = t;
            swts [slot] = sv / ws;
        }
    }
}

// ---------------- tf32 mma.sync GEMM, transposeless B ----------------
// Modes: H!=0 -> fused-SwiGLU out (split-half B cols, gOff>0);
//        cIdx!=0 -> fused weighted atomic combine into D (token-major);
//        else plain D store.
#define ROWB 144
#define BROW 544
#define A_BYTES 18432
#define STG_BYTES 35840

__device__ __forceinline__ void issue_stage(
    uint32_t sdst, const float* __restrict__ pA, const float* __restrict__ pB,
    int K, int N, int kcol, int n0, int gOff, int tid, const int* ar) {
    #pragma unroll
    for (int i = 0; i < 4; i++) {
        int id = tid + 256 * i;
        int row = id >> 3, c16 = id & 7;
        uint32_t so = (uint32_t)(row * ROWB + c16 * 16);
        CP_ASYNC16(sdst + so, pA + (size_t)ar[i] * K + kcol + c16 * 4);
    }
    int hb = n0 >> 1;
    #pragma unroll
    for (int i = 0; i < 4; i++) {
        int id = tid + 256 * i;
        int kr = id >> 5, ch = id & 31;
        int col;
        if (gOff) col = (ch < 16) ? (hb + ch * 4) : (gOff + hb + (ch - 16) * 4);
        else      col = n0 + ch * 4;
        CP_ASYNC16(sdst + A_BYTES + (uint32_t)(kr * BROW + ch * 16),
                   pB + (size_t)(kcol + kr) * N + col);
    }
}

__global__ __launch_bounds__(256, 2) void gemm_kernel(
    const float* __restrict__ A, const float* __restrict__ B,
    float* __restrict__ D, float* __restrict__ H,
    int M, int N, int K, int gOff,
    long sAz, long sBz, long sDz,
    const int* __restrict__ counts, const int* __restrict__ rowidx,
    const int* __restrict__ cIdx, const float* __restrict__ cW) {
    extern __shared__ __align__(128) char smem[];
    int z = blockIdx.z;
    if (counts) M = counts[z];
    int m0 = blockIdx.y * 128;
    if (m0 >= M) return;
    int n0 = blockIdx.x * 128;
    A += (size_t)z * sAz; B += (size_t)z * sBz;

    int tid = threadIdx.x, wid = tid >> 5, lane = tid & 31;
    int wm = (wid & 1) * 64;
    uint32_t sbase = smem_u32(smem);

    const float* pA;
    int ar[4];
    if (rowidx) {
        const int* ridx = rowidx + (size_t)z * CAP + m0;
        pA = A;
        #pragma unroll
        for (int i = 0; i < 4; i++) ar[i] = ridx[(tid >> 3) + 32 * i];
    } else {
        pA = A + (size_t)m0 * K;
        #pragma unroll
        for (int i = 0; i < 4; i++) ar[i] = (tid >> 3) + 32 * i;
    }

    float acc[4][4][4];
    #pragma unroll
    for (int i = 0; i < 4; i++)
        #pragma unroll
        for (int j = 0; j < 4; j++)
            #pragma unroll
            for (int r = 0; r < 4; r++) acc[i][j][r] = 0.f;

    const int nk = K >> 5;
    issue_stage(sbase,             pA, B, K, N, 0,  n0, gOff, tid, ar); CP_COMMIT();
    issue_stage(sbase + STG_BYTES, pA, B, K, N, 32, n0, gOff, tid, ar); CP_COMMIT();

    uint32_t aoff = (uint32_t)((wm + (lane & 15)) * ROWB + ((lane >> 4) & 1) * 16);
    int sbg[4];
    if (gOff) {
        int wny = (wid >> 1) * 16;
        #pragma unroll
        for (int g = 0; g < 4; g++) sbg[g] = ((g & 2) ? 64 : 0) + wny + (g & 1) * 8;
    } else {
        int wn = (wid >> 1) * 32;
        #pragma unroll
        for (int g = 0; g < 4; g++) sbg[g] = wn + g * 8;
    }
    uint32_t brow0 = (uint32_t)((lane & 3) * BROW);
    uint32_t blane = (uint32_t)((lane >> 2) * 4);

    int stg = 0;
    for (int kc = 0; kc < nk; kc++) {
        CP_WAIT1();
        __syncthreads();
        if (kc + 2 < nk) {
            int nx = stg + 2; if (nx >= 3) nx -= 3;
            issue_stage(sbase + nx * STG_BYTES, pA, B, K, N, (kc + 2) * 32, n0, gOff, tid, ar);
        }
        CP_COMMIT();

        uint32_t sA = sbase + stg * STG_BYTES;
        uint32_t sB = sA + A_BYTES + brow0 + blane;
        #pragma unroll
        for (int s = 0; s < 4; s++) {
            uint32_t a[4][4];
            #pragma unroll
            for (int mi = 0; mi < 4; mi++)
                ldm_x4(a[mi], sA + aoff + (uint32_t)(mi * 16 * ROWB + s * 32));
            #pragma unroll
            for (int g = 0; g < 4; g++) {
                uint32_t b[2];
                uint32_t ba = sB + (uint32_t)(s * 8 * BROW + sbg[g] * 4);
                LDS32(b[0], ba);
                LDS32(b[1], ba + 4 * BROW);
                b[0] = cvt_tf32_u(b[0]);
                b[1] = cvt_tf32_u(b[1]);
                #pragma unroll
                for (int mi = 0; mi < 4; mi++)
                    mma_tf32(acc[mi][g], a[mi], b);
            }
        }
        if (++stg == 3) stg = 0;
    }

    int r0 = lane >> 2, c0 = (lane & 3) * 2;
    if (H) {
        // fused SwiGLU: y = groups 0,1 ; gate = groups 2,3 (same register slots)
        int halfN = N >> 1;
        int hb = n0 >> 1;
        int wny = (wid >> 1) * 16;
        H += (size_t)z * sDz;
        #pragma unroll
        for (int mi = 0; mi < 4; mi++) {
            #pragma unroll
            for (int g = 0; g < 2; g++) {
                int row = m0 + wm + mi * 16 + r0;
                int hcol = hb + wny + g * 8 + c0;
                float y0 = acc[mi][g][0], gg0 = acc[mi][g + 2][0];
                float y1 = acc[mi][g][1], gg1 = acc[mi][g + 2][1];
                float y2 = acc[mi][g][2], gg2 = acc[mi][g + 2][2];
                float y3 = acc[mi][g][3], gg3 = acc[mi][g + 2][3];
                H[(size_t)row * halfN + hcol]           = to_tf32(y0 * gg0 / (1.f + __expf(-gg0)));
                H[(size_t)row * halfN + hcol + 1]       = to_tf32(y1 * gg1 / (1.f + __expf(-gg1)));
                H[(size_t)(row + 8) * halfN + hcol]     = to_tf32(y2 * gg2 / (1.f + __expf(-gg2)));
                H[(size_t)(row + 8) * halfN + hcol + 1] = to_tf32(y3 * gg3 / (1.f + __expf(-gg3)));
            }
        }
    } else if (cIdx) {
        // fused weighted combine: out[token] += w * val (guard rows >= count)
        const int* ridx = cIdx + (size_t)z * CAP;
        const float* wv = cW + (size_t)z * CAP;
        int wn = (wid >> 1) * 32;
        #pragma unroll
        for (int mi = 0; mi < 4; mi++) {
            int row = m0 + wm + mi * 16 + r0;
            #pragma unroll
            for (int h = 0; h < 2; h++) {
                int rr = row + h * 8;
                if (rr < M) {
                    int tt = ridx[rr];
                    float w = wv[rr];
                    float* O = D + (size_t)tt * CDIM;
                    #pragma unroll
                    for (int g = 0; g < 4; g++) {
                        int col = n0 + wn + g * 8 + c0;
                        atomicAdd(O + col,     w * acc[mi][g][h * 2]);
                        atomicAdd(O + col + 1, w * acc[mi][g][h * 2 + 1]);
                    }
                }
            }
        }
    } else {
        D += (size_t)z * sDz;
        int wn = (wid >> 1) * 32;
        #pragma unroll
        for (int mi = 0; mi < 4; mi++) {
            #pragma unroll
            for (int g = 0; g < 4; g++) {
                int row = m0 + wm + mi * 16 + r0;
                int col = n0 + wn + g * 8 + c0;
                *(float2*)(D + (size_t)row * N + col) = make_float2(acc[mi][g][0], acc[mi][g][1]);
                *(float2*)(D + (size_t)(row + 8) * N + col) = make_float2(acc[mi][g][2], acc[mi][g][3]);
            }
        }
    }
}

// ---------------- launch (two-stream DAG, graph-capturable fork/join) ----------------
extern "C" void kernel_launch(void* const* d_in, const int* in_sizes, int n_in,
                              void* d_out, int out_size) {
    const float* x       = (const float*)d_in[0];
    const float* rw      = (const float*)d_in[1];
    const float* bias    = (const float*)d_in[2];
    const float* sup_w   = (const float*)d_in[3];
    const float* sdown_w = (const float*)d_in[4];
    const float* eup_w   = (const float*)d_in[5];
    const float* edown_w = (const float*)d_in[6];
    float* out = (float*)d_out;
    (void)in_sizes; (void)n_in; (void)out_size;

    float *xr, *sh, *eh, *swts;
    int *counts, *rowidx;
    cudaGetSymbolAddress((void**)&xr, g_xr);
    cudaGetSymbolAddress((void**)&sh, g_sh);
    cudaGetSymbolAddress((void**)&eh, g_eh);
    cudaGetSymbolAddress((void**)&swts, g_swts);
    cudaGetSymbolAddress((void**)&counts, g_counts);
    cudaGetSymbolAddress((void**)&rowidx, g_rowidx);

    cudaFuncSetAttribute(gemm_kernel, cudaFuncAttributeMaxDynamicSharedMemorySize, 3 * STG_BYTES);
    const int gsmem = 3 * STG_BYTES;

    static cudaStream_t s1 = nullptr;
    static cudaEvent_t evFork = nullptr, evXr = nullptr, evS1 = nullptr;
    if (!s1) {
        cudaStreamCreateWithFlags(&s1, cudaStreamNonBlocking);
        cudaEventCreateWithFlags(&evFork, cudaEventDisableTiming);
        cudaEventCreateWithFlags(&evXr, cudaEventDisableTiming);
        cudaEventCreateWithFlags(&evS1, cudaEventDisableTiming);
    }

    // ---- fork ----
    cudaEventRecord(evFork, 0);
    cudaStreamWaitEvent(s1, evFork, 0);

    // main: routing
    zero_counts_kernel<<<1, 64>>>(counts);
    router_kernel<<<NTOK, 256>>>(x, rw, bias, counts, rowidx, swts);

    // s1: xr -> shared-up -> shared-down (writes out)
    xr_kernel<<<NTOK * CDIM / 4 / 256, 256, 0, s1>>>(x, xr);
    cudaEventRecord(evXr, s1);
    gemm_kernel<<<dim3(2 * HS / 128, NTOK / 128, 1), 256, gsmem, s1>>>(
        xr, sup_w, nullptr, sh, NTOK, 2 * HS, CDIM, HS, 0, 0, 0,
        nullptr, nullptr, nullptr, nullptr);
    gemm_kernel<<<dim3(CDIM / 128, NTOK / 128, 1), 256, gsmem, s1>>>(
        sh, sdown_w, out, nullptr, NTOK, CDIM, HS, 0, 0, 0, 0,
        nullptr, nullptr, nullptr, nullptr);
    cudaEventRecord(evS1, s1);

    // main: expert-up (needs xr + router) -> expert-down (atomic combine into out)
    cudaStreamWaitEvent(0, evXr, 0);
    gemm_kernel<<<dim3(2 * HE / 128, CAP / 128, NEXP), 256, gsmem>>>(
        xr, eup_w, nullptr, eh, CAP, 2 * HE, CDIM, HE,
        0, (long)CDIM * (2 * HE), (long)CAP * HE, counts, rowidx, nullptr, nullptr);
    cudaStreamWaitEvent(0, evS1, 0);
    gemm_kernel<<<dim3(CDIM / 128, CAP / 128, NEXP), 256, gsmem>>>(
        eh, edown_w, out, nullptr, CAP, CDIM, HE, 0,
        (long)CAP * HE, (long)HE * CDIM, 0, counts, nullptr, rowidx, swts);
}

// round 15
// speedup vs baseline: 1.1764x; 1.0212x over previous
#include <cuda_runtime.h>
#include <cuda_bf16.h>
#include <cstdint>

// ---------------- shapes ----------------
#define NTOK 4096
#define CDIM 1024
#define NEXP 64
#define TOPK 8
#define CAP  1024
#define HS   1024
#define HE   512

// ---------------- helpers ----------------
__device__ __forceinline__ uint32_t smem_u32(const void* p) {
    uint32_t a;
    asm("{ .reg .u64 t; cvta.to.shared.u64 t, %1; cvt.u32.u64 %0, t; }" : "=r"(a) : "l"(p));
    return a;
}
#define CP_ASYNC16(dst, src) \
    asm volatile("cp.async.cg.shared.global [%0], [%1], 16;" :: "r"(dst), "l"(src))
#define CP_COMMIT() asm volatile("cp.async.commit_group;" ::: "memory")
#define CP_WAIT1()  asm volatile("cp.async.wait_group 1;" ::: "memory")

__device__ __forceinline__ void ldm_x4(uint32_t* r, uint32_t addr) {
    asm volatile("ldmatrix.sync.aligned.m8n8.x4.shared.b16 {%0,%1,%2,%3}, [%4];"
        : "=r"(r[0]), "=r"(r[1]), "=r"(r[2]), "=r"(r[3]) : "r"(addr));
}
#define LDS32(r, addr) \
    asm volatile("ld.shared.b32 %0, [%1];" : "=r"(r) : "r"(addr))
__device__ __forceinline__ void mma_tf32(float* d, const uint32_t* a, const uint32_t* b) {
    asm volatile(
        "mma.sync.aligned.m16n8k8.row.col.f32.tf32.tf32.f32 "
        "{%0,%1,%2,%3}, {%4,%5,%6,%7}, {%8,%9}, {%0,%1,%2,%3};"
        : "+f"(d[0]), "+f"(d[1]), "+f"(d[2]), "+f"(d[3])
        : "r"(a[0]), "r"(a[1]), "r"(a[2]), "r"(a[3]), "r"(b[0]), "r"(b[1]));
}
__device__ __forceinline__ float to_tf32(float v) {
    uint32_t r;
    asm("cvt.rna.tf32.f32 %0, %1;" : "=r"(r) : "f"(v));
    return __uint_as_float(r);
}
__device__ __forceinline__ uint32_t cvt_tf32_u(uint32_t raw) {
    uint32_t r;
    asm("cvt.rna.tf32.f32 %0, %1;" : "=r"(r) : "r"(raw));
    return r;
}

// ---------------- scratch (device globals) ----------------
__device__ float g_xr  [(size_t)NTOK * CDIM];
__device__ float g_sh  [(size_t)NTOK * HS];
__device__ float g_eh  [(size_t)NEXP * CAP * HE];
__device__ int   g_counts[NEXP];
__device__ int   g_rowidx[NEXP * CAP];
__device__ float g_swts [NEXP * CAP];

// ---------------- zero counts ----------------
__global__ void zero_counts_kernel(int* counts) {
    if (threadIdx.x < NEXP) counts[threadIdx.x] = 0;
}

// ---------------- zero out buffer ----------------
__global__ void zero_out_kernel(float* __restrict__ out) {
    size_t i = (size_t)blockIdx.x * blockDim.x + threadIdx.x;
    *(float4*)(out + i * 4) = make_float4(0.f, 0.f, 0.f, 0.f);
}

// ---------------- xr: tf32-round x ----------------
__global__ void xr_kernel(const float* __restrict__ x, float* __restrict__ xr) {
    size_t i4 = (size_t)blockIdx.x * blockDim.x + threadIdx.x;
    if (i4 >= (size_t)NTOK * CDIM / 4) return;
    float4 v = *(const float4*)(x + i4 * 4);
    v.x = to_tf32(v.x); v.y = to_tf32(v.y);
    v.z = to_tf32(v.z); v.w = to_tf32(v.w);
    *(float4*)(xr + i4 * 4) = v;
}

// ---------------- router: scores, warp top-8, slot assign (rowidx + swts) ----------------
__global__ __launch_bounds__(256) void router_kernel(
    const float* __restrict__ x, const float* __restrict__ rw, const float* __restrict__ bias,
    int* __restrict__ counts, int* __restrict__ rowidx, float* __restrict__ swts) {
    int t = blockIdx.x;
    int tid = threadIdx.x;
    __shared__ float xs[CDIM];
    __shared__ float partial[256];
    __shared__ float sc[NEXP];
    __shared__ float sb[NEXP];

    for (int i = tid; i < CDIM; i += 256) xs[i] = x[(size_t)t * CDIM + i];
    __syncthreads();

    int e = tid & 63, part = tid >> 6;
    float acc = 0.f;
    const float* rwp = rw + (size_t)(part * 256) * NEXP + e;
    #pragma unroll 8
    for (int c = 0; c < 256; c++) acc += xs[part * 256 + c] * rwp[(size_t)c * NEXP];
    partial[tid] = acc;
    __syncthreads();
    if (tid < NEXP) {
        float v = partial[tid] + partial[tid + 64] + partial[tid + 128] + partial[tid + 192];
        float s = 1.f / (1.f + __expf(-v));
        sc[tid] = s;
        sb[tid] = s + bias[tid];
    }
    __syncthreads();

    if (tid < 32) {
        float v0 = sb[tid], v1 = sb[tid + 32];
        int eid = 0;
        #pragma unroll
        for (int k = 0; k < TOPK; k++) {
            float m; int me;
            if (v0 >= v1) { m = v0; me = tid; } else { m = v1; me = tid + 32; }
            #pragma unroll
            for (int off = 16; off; off >>= 1) {
                float om = __shfl_down_sync(0xffffffffu, m, off);
                int   oe = __shfl_down_sync(0xffffffffu, me, off);
                if (om > m) { m = om; me = oe; }
            }
            me = __shfl_sync(0xffffffffu, me, 0);
            if (tid == me) v0 = -1e30f;
            if (tid == me - 32) v1 = -1e30f;
            if (tid == k) eid = me;
        }
        float sv = (tid < TOPK) ? sc[eid] : 0.f;
        float ws = sv;
        #pragma unroll
        for (int off = 4; off; off >>= 1) ws += __shfl_down_sync(0xffffffffu, ws, off, 8);
        ws = __shfl_sync(0xffffffffu, ws, 0);
        if (tid < TOPK) {
            int pos  = atomicAdd(&counts[eid], 1);
            int slot = eid * CAP + pos;
            rowidx[slot] = t;
            swts [slot] = sv / ws;
        }
    }
}

// ---------------- tf32 mma.sync GEMM, transposeless B ----------------
// Modes: H!=0 -> fused-SwiGLU out (split-half B, gOff>0);
//        cIdx!=0 -> weighted gather atomic combine into D;
//        atomicD -> direct atomicAdd into D;
//        else plain store.
#define ROWB 144
#define BROW 544
#define A_BYTES 18432
#define STG_BYTES 35840

__device__ __forceinline__ void issue_stage(
    uint32_t sdst, const float* __restrict__ pA, const float* __restrict__ pB,
    int K, int N, int kcol, int n0, int gOff, int tid, const int* ar) {
    #pragma unroll
    for (int i = 0; i < 4; i++) {
        int id = tid + 256 * i;
        int row = id >> 3, c16 = id & 7;
        uint32_t so = (uint32_t)(row * ROWB + c16 * 16);
        CP_ASYNC16(sdst + so, pA + (size_t)ar[i] * K + kcol + c16 * 4);
    }
    int hb = n0 >> 1;
    #pragma unroll
    for (int i = 0; i < 4; i++) {
        int id = tid + 256 * i;
        int kr = id >> 5, ch = id & 31;
        int col;
        if (gOff) col = (ch < 16) ? (hb + ch * 4) : (gOff + hb + (ch - 16) * 4);
        else      col = n0 + ch * 4;
        CP_ASYNC16(sdst + A_BYTES + (uint32_t)(kr * BROW + ch * 16),
                   pB + (size_t)(kcol + kr) * N + col);
    }
}

__global__ __launch_bounds__(256, 2) void gemm_kernel(
    const float* __restrict__ A, const float* __restrict__ B,
    float* __restrict__ D, float* __restrict__ H,
    int M, int N, int K, int gOff, int atomicD,
    long sAz, long sBz, long sDz,
    const int* __restrict__ counts, const int* __restrict__ rowidx,
    const int* __restrict__ cIdx, const float* __restrict__ cW) {
    extern __shared__ __align__(128) char smem[];
    int z = blockIdx.z;
    if (counts) M = counts[z];
    int m0 = blockIdx.y * 128;
    if (m0 >= M) return;
    int n0 = blockIdx.x * 128;
    A += (size_t)z * sAz; B += (size_t)z * sBz;

    int tid = threadIdx.x, wid = tid >> 5, lane = tid & 31;
    int wm = (wid & 1) * 64;
    uint32_t sbase = smem_u32(smem);

    const float* pA;
    int ar[4];
    if (rowidx) {
        const int* ridx = rowidx + (size_t)z * CAP + m0;
        pA = A;
        #pragma unroll
        for (int i = 0; i < 4; i++) ar[i] = ridx[(tid >> 3) + 32 * i];
    } else {
        pA = A + (size_t)m0 * K;
        #pragma unroll
        for (int i = 0; i < 4; i++) ar[i] = (tid >> 3) + 32 * i;
    }

    float acc[4][4][4];
    #pragma unroll
    for (int i = 0; i < 4; i++)
        #pragma unroll
        for (int j = 0; j < 4; j++)
            #pragma unroll
            for (int r = 0; r < 4; r++) acc[i][j][r] = 0.f;

    const int nk = K >> 5;
    issue_stage(sbase,             pA, B, K, N, 0,  n0, gOff, tid, ar); CP_COMMIT();
    issue_stage(sbase + STG_BYTES, pA, B, K, N, 32, n0, gOff, tid, ar); CP_COMMIT();

    uint32_t aoff = (uint32_t)((wm + (lane & 15)) * ROWB + ((lane >> 4) & 1) * 16);
    int sbg[4];
    if (gOff) {
        int wny = (wid >> 1) * 16;
        #pragma unroll
        for (int g = 0; g < 4; g++) sbg[g] = ((g & 2) ? 64 : 0) + wny + (g & 1) * 8;
    } else {
        int wn = (wid >> 1) * 32;
        #pragma unroll
        for (int g = 0; g < 4; g++) sbg[g] = wn + g * 8;
    }
    uint32_t brow0 = (uint32_t)((lane & 3) * BROW);
    uint32_t blane = (uint32_t)((lane >> 2) * 4);

    int stg = 0;
    for (int kc = 0; kc < nk; kc++) {
        CP_WAIT1();
        __syncthreads();
        if (kc + 2 < nk) {
            int nx = stg + 2; if (nx >= 3) nx -= 3;
            issue_stage(sbase + nx * STG_BYTES, pA, B, K, N, (kc + 2) * 32, n0, gOff, tid, ar);
        }
        CP_COMMIT();

        uint32_t sA = sbase + stg * STG_BYTES;
        uint32_t sB = sA + A_BYTES + brow0 + blane;
        #pragma unroll
        for (int s = 0; s < 4; s++) {
            uint32_t a[4][4];
            #pragma unroll
            for (int mi = 0; mi < 4; mi++)
                ldm_x4(a[mi], sA + aoff + (uint32_t)(mi * 16 * ROWB + s * 32));
            #pragma unroll
            for (int g = 0; g < 4; g++) {
                uint32_t b[2];
                uint32_t ba = sB + (uint32_t)(s * 8 * BROW + sbg[g] * 4);
                LDS32(b[0], ba);
                LDS32(b[1], ba + 4 * BROW);
                b[0] = cvt_tf32_u(b[0]);
                b[1] = cvt_tf32_u(b[1]);
                #pragma unroll
                for (int mi = 0; mi < 4; mi++)
                    mma_tf32(acc[mi][g], a[mi], b);
            }
        }
        if (++stg == 3) stg = 0;
    }

    int r0 = lane >> 2, c0 = (lane & 3) * 2;
    if (H) {
        // fused SwiGLU: y = groups 0,1 ; gate = groups 2,3 (same register slots)
        int halfN = N >> 1;
        int hb = n0 >> 1;
        int wny = (wid >> 1) * 16;
        H += (size_t)z * sDz;
        #pragma unroll
        for (int mi = 0; mi < 4; mi++) {
            #pragma unroll
            for (int g = 0; g < 2; g++) {
                int row = m0 + wm + mi * 16 + r0;
                int hcol = hb + wny + g * 8 + c0;
                float y0 = acc[mi][g][0], gg0 = acc[mi][g + 2][0];
                float y1 = acc[mi][g][1], gg1 = acc[mi][g + 2][1];
                float y2 = acc[mi][g][2], gg2 = acc[mi][g + 2][2];
                float y3 = acc[mi][g][3], gg3 = acc[mi][g + 2][3];
                H[(size_t)row * halfN + hcol]           = to_tf32(y0 * gg0 / (1.f + __expf(-gg0)));
                H[(size_t)row * halfN + hcol + 1]       = to_tf32(y1 * gg1 / (1.f + __expf(-gg1)));
                H[(size_t)(row + 8) * halfN + hcol]     = to_tf32(y2 * gg2 / (1.f + __expf(-gg2)));
                H[(size_t)(row + 8) * halfN + hcol + 1] = to_tf32(y3 * gg3 / (1.f + __expf(-gg3)));
            }
        }
    } else if (cIdx) {
        // fused weighted combine: out[token] += w * val (guard rows >= count)
        const int* ridx = cIdx + (size_t)z * CAP;
        const float* wv = cW + (size_t)z * CAP;
        int wn = (wid >> 1) * 32;
        #pragma unroll
        for (int mi = 0; mi < 4; mi++) {
            int row = m0 + wm + mi * 16 + r0;
            #pragma unroll
            for (int h = 0; h < 2; h++) {
                int rr = row + h * 8;
                if (rr < M) {
                    int tt = ridx[rr];
                    float w = wv[rr];
                    float* O = D + (size_t)tt * CDIM;
                    #pragma unroll
                    for (int g = 0; g < 4; g++) {
                        int col = n0 + wn + g * 8 + c0;
                        atomicAdd(O + col,     w * acc[mi][g][h * 2]);
                        atomicAdd(O + col + 1, w * acc[mi][g][h * 2 + 1]);
                    }
                }
            }
        }
    } else if (atomicD) {
        // direct atomic accumulate (shared-down path)
        int wn = (wid >> 1) * 32;
        #pragma unroll
        for (int mi = 0; mi < 4; mi++) {
            #pragma unroll
            for (int g = 0; g < 4; g++) {
                int row = m0 + wm + mi * 16 + r0;
                int col = n0 + wn + g * 8 + c0;
                atomicAdd(D + (size_t)row * N + col,     acc[mi][g][0]);
                atomicAdd(D + (size_t)row * N + col + 1, acc[mi][g][1]);
                atomicAdd(D + (size_t)(row + 8) * N + col,     acc[mi][g][2]);
                atomicAdd(D + (size_t)(row + 8) * N + col + 1, acc[mi][g][3]);
            }
        }
    } else {
        D += (size_t)z * sDz;
        int wn = (wid >> 1) * 32;
        #pragma unroll
        for (int mi = 0; mi < 4; mi++) {
            #pragma unroll
            for (int g = 0; g < 4; g++) {
                int row = m0 + wm + mi * 16 + r0;
                int col = n0 + wn + g * 8 + c0;
                *(float2*)(D + (size_t)row * N + col) = make_float2(acc[mi][g][0], acc[mi][g][1]);
                *(float2*)(D + (size_t)(row + 8) * N + col) = make_float2(acc[mi][g][2], acc[mi][g][3]);
            }
        }
    }
}

// ---------------- launch (two-stream DAG, graph-capturable fork/join) ----------------
extern "C" void kernel_launch(void* const* d_in, const int* in_sizes, int n_in,
                              void* d_out, int out_size) {
    const float* x       = (const float*)d_in[0];
    const float* rw      = (const float*)d_in[1];
    const float* bias    = (const float*)d_in[2];
    const float* sup_w   = (const float*)d_in[3];
    const float* sdown_w = (const float*)d_in[4];
    const float* eup_w   = (const float*)d_in[5];
    const float* edown_w = (const float*)d_in[6];
    float* out = (float*)d_out;
    (void)in_sizes; (void)n_in; (void)out_size;

    float *xr, *sh, *eh, *swts;
    int *counts, *rowidx;
    cudaGetSymbolAddress((void**)&xr, g_xr);
    cudaGetSymbolAddress((void**)&sh, g_sh);
    cudaGetSymbolAddress((void**)&eh, g_eh);
    cudaGetSymbolAddress((void**)&swts, g_swts);
    cudaGetSymbolAddress((void**)&counts, g_counts);
    cudaGetSymbolAddress((void**)&rowidx, g_rowidx);

    cudaFuncSetAttribute(gemm_kernel, cudaFuncAttributeMaxDynamicSharedMemorySize, 3 * STG_BYTES);
    const int gsmem = 3 * STG_BYTES;

    static cudaStream_t s1 = nullptr;
    static cudaEvent_t evFork = nullptr, evXr = nullptr;
    if (!s1) {
        cudaStreamCreateWithFlags(&s1, cudaStreamNonBlocking);
        cudaEventCreateWithFlags(&evFork, cudaEventDisableTiming);
        cudaEventCreateWithFlags(&evXr, cudaEventDisableTiming);
    }

    // main: zero out accumulator + counts, then fork
    zero_out_kernel<<<NTOK * CDIM / 4 / 256, 256>>>(out);
    zero_counts_kernel<<<1, 64>>>(counts);
    cudaEventRecord(evFork, 0);
    cudaStreamWaitEvent(s1, evFork, 0);

    // main: router
    router_kernel<<<NTOK, 256>>>(x, rw, bias, counts, rowidx, swts);

    // s1: xr -> shared-up -> shared-down (atomic accumulate into out)
    xr_kernel<<<NTOK * CDIM / 4 / 256, 256, 0, s1>>>(x, xr);
    cudaEventRecord(evXr, s1);
    gemm_kernel<<<dim3(2 * HS / 128, NTOK / 128, 1), 256, gsmem, s1>>>(
        xr, sup_w, nullptr, sh, NTOK, 2 * HS, CDIM, HS, 0, 0, 0, 0,
        nullptr, nullptr, nullptr, nullptr);
    gemm_kernel<<<dim3(CDIM / 128, NTOK / 128, 1), 256, gsmem, s1>>>(
        sh, sdown_w, out, nullptr, NTOK, CDIM, HS, 0, 1, 0, 0, 0,
        nullptr, nullptr, nullptr, nullptr);

    // main: expert-up (needs xr + router) -> expert-down (weighted atomic combine)
    cudaStreamWaitEvent(0, evXr, 0);
    gemm_kernel<<<dim3(2 * HE / 128, CAP / 128, NEXP), 256, gsmem>>>(
        xr, eup_w, nullptr, eh, CAP, 2 * HE, CDIM, HE, 0,
        0, (long)CDIM * (2 * HE), (long)CAP * HE, counts, rowidx, nullptr, nullptr);
    gemm_kernel<<<dim3(CDIM / 128, CAP / 128, NEXP), 256, gsmem>>>(
        eh, edown_w, out, nullptr, CAP, CDIM, HE, 0, 0,
        (long)CAP * HE, (long)HE * CDIM, 0, counts, nullptr, rowidx, swts);

    // join: main waits for s1 (shared chain) before kernel_launch returns work
    cudaEventRecord(evFork, s1);          // reuse event as join marker
    cudaStreamWaitEvent(0, evFork, 0);
}

// round 17
// speedup vs baseline: 1.1774x; 1.0009x over previous
#include <cuda_runtime.h>
#include <cuda_bf16.h>
#include <cstdint>

// ---------------- shapes ----------------
#define NTOK 4096
#define CDIM 1024
#define NEXP 64
#define TOPK 8
#define CAP  1024
#define HS   1024
#define HE   512
#define EHALF 32   // experts per half

// ---------------- helpers ----------------
__device__ __forceinline__ uint32_t smem_u32(const void* p) {
    uint32_t a;
    asm("{ .reg .u64 t; cvta.to.shared.u64 t, %1; cvt.u32.u64 %0, t; }" : "=r"(a) : "l"(p));
    return a;
}
#define CP_ASYNC16(dst, src) \
    asm volatile("cp.async.cg.shared.global [%0], [%1], 16;" :: "r"(dst), "l"(src))
#define CP_COMMIT() asm volatile("cp.async.commit_group;" ::: "memory")
#define CP_WAIT1()  asm volatile("cp.async.wait_group 1;" ::: "memory")

__device__ __forceinline__ void ldm_x4(uint32_t* r, uint32_t addr) {
    asm volatile("ldmatrix.sync.aligned.m8n8.x4.shared.b16 {%0,%1,%2,%3}, [%4];"
        : "=r"(r[0]), "=r"(r[1]), "=r"(r[2]), "=r"(r[3]) : "r"(addr));
}
#define LDS32(r, addr) \
    asm volatile("ld.shared.b32 %0, [%1];" : "=r"(r) : "r"(addr))
__device__ __forceinline__ void mma_tf32(float* d, const uint32_t* a, const uint32_t* b) {
    asm volatile(
        "mma.sync.aligned.m16n8k8.row.col.f32.tf32.tf32.f32 "
        "{%0,%1,%2,%3}, {%4,%5,%6,%7}, {%8,%9}, {%0,%1,%2,%3};"
        : "+f"(d[0]), "+f"(d[1]), "+f"(d[2]), "+f"(d[3])
        : "r"(a[0]), "r"(a[1]), "r"(a[2]), "r"(a[3]), "r"(b[0]), "r"(b[1]));
}
__device__ __forceinline__ float to_tf32(float v) {
    uint32_t r;
    asm("cvt.rna.tf32.f32 %0, %1;" : "=r"(r) : "f"(v));
    return __uint_as_float(r);
}
__device__ __forceinline__ uint32_t cvt_tf32_u(uint32_t raw) {
    uint32_t r;
    asm("cvt.rna.tf32.f32 %0, %1;" : "=r"(r) : "r"(raw));
    return r;
}

// ---------------- scratch (device globals) ----------------
__device__ float g_xr  [(size_t)NTOK * CDIM];
__device__ float g_sh  [(size_t)NTOK * HS];
__device__ float g_eh  [(size_t)NEXP * CAP * HE];
__device__ int   g_counts[NEXP];
__device__ int   g_rowidx[NEXP * CAP];
__device__ float g_swts [NEXP * CAP];

// ---------------- zero counts ----------------
__global__ void zero_counts_kernel(int* counts) {
    if (threadIdx.x < NEXP) counts[threadIdx.x] = 0;
}

// ---------------- zero out buffer ----------------
__global__ void zero_out_kernel(float* __restrict__ out) {
    size_t i = (size_t)blockIdx.x * blockDim.x + threadIdx.x;
    *(float4*)(out + i * 4) = make_float4(0.f, 0.f, 0.f, 0.f);
}

// ---------------- xr: tf32-round x ----------------
__global__ void xr_kernel(const float* __restrict__ x, float* __restrict__ xr) {
    size_t i4 = (size_t)blockIdx.x * blockDim.x + threadIdx.x;
    if (i4 >= (size_t)NTOK * CDIM / 4) return;
    float4 v = *(const float4*)(x + i4 * 4);
    v.x = to_tf32(v.x); v.y = to_tf32(v.y);
    v.z = to_tf32(v.z); v.w = to_tf32(v.w);
    *(float4*)(xr + i4 * 4) = v;
}

// ---------------- router ----------------
__global__ __launch_bounds__(256) void router_kernel(
    const float* __restrict__ x, const float* __restrict__ rw, const float* __restrict__ bias,
    int* __restrict__ counts, int* __restrict__ rowidx, float* __restrict__ swts) {
    int t = blockIdx.x;
    int tid = threadIdx.x;
    __shared__ float xs[CDIM];
    __shared__ float partial[256];
    __shared__ float sc[NEXP];
    __shared__ float sb[NEXP];

    for (int i = tid; i < CDIM; i += 256) xs[i] = x[(size_t)t * CDIM + i];
    __syncthreads();

    int e = tid & 63, part = tid >> 6;
    float acc = 0.f;
    const float* rwp = rw + (size_t)(part * 256) * NEXP + e;
    #pragma unroll 8
    for (int c = 0; c < 256; c++) acc += xs[part * 256 + c] * rwp[(size_t)c * NEXP];
    partial[tid] = acc;
    __syncthreads();
    if (tid < NEXP) {
        float v = partial[tid] + partial[tid + 64] + partial[tid + 128] + partial[tid + 192];
        float s = 1.f / (1.f + __expf(-v));
        sc[tid] = s;
        sb[tid] = s + bias[tid];
    }
    __syncthreads();

    if (tid < 32) {
        float v0 = sb[tid], v1 = sb[tid + 32];
        int eid = 0;
        #pragma unroll
        for (int k = 0; k < TOPK; k++) {
            float m; int me;
            if (v0 >= v1) { m = v0; me = tid; } else { m = v1; me = tid + 32; }
            #pragma unroll
            for (int off = 16; off; off >>= 1) {
                float om = __shfl_down_sync(0xffffffffu, m, off);
                int   oe = __shfl_down_sync(0xffffffffu, me, off);
                if (om > m) { m = om; me = oe; }
            }
            me = __shfl_sync(0xffffffffu, me, 0);
            if (tid == me) v0 = -1e30f;
            if (tid == me - 32) v1 = -1e30f;
            if (tid == k) eid = me;
        }
        float sv = (tid < TOPK) ? sc[eid] : 0.f;
        float ws = sv;
        #pragma unroll
        for (int off = 4; off; off >>= 1) ws += __shfl_down_sync(0xffffffffu, ws, off, 8);
        ws = __shfl_sync(0xffffffffu, ws, 0);
        if (tid < TOPK) {
            int pos  = atomicAdd(&counts[eid], 1);
            int slot = eid * CAP + pos;
            rowidx[slot] = t;
            swts [slot] = sv / ws;
        }
    }
}

// ---------------- tf32 mma.sync GEMM, transposeless B ----------------
#define ROWB 144
#define BROW 544
#define A_BYTES 18432
#define STG_BYTES 35840

__device__ __forceinline__ void issue_stage(
    uint32_t sdst, const float* __restrict__ pA, const float* __restrict__ pB,
    int K, int N, int kcol, int n0, int gOff, int tid, const int* ar) {
    #pragma unroll
    for (int i = 0; i < 4; i++) {
        int id = tid + 256 * i;
        int row = id >> 3, c16 = id & 7;
        uint32_t so = (uint32_t)(row * ROWB + c16 * 16);
        CP_ASYNC16(sdst + so, pA + (size_t)ar[i] * K + kcol + c16 * 4);
    }
    int hb = n0 >> 1;
    #pragma unroll
    for (int i = 0; i < 4; i++) {
        int id = tid + 256 * i;
        int kr = id >> 5, ch = id & 31;
        int col;
        if (gOff) col = (ch < 16) ? (hb + ch * 4) : (gOff + hb + (ch - 16) * 4);
        else      col = n0 + ch * 4;
        CP_ASYNC16(sdst + A_BYTES + (uint32_t)(kr * BROW + ch * 16),
                   pB + (size_t)(kcol + kr) * N + col);
    }
}

__global__ __launch_bounds__(256, 2) void gemm_kernel(
    const float* __restrict__ A, const float* __restrict__ B,
    float* __restrict__ D, float* __restrict__ H,
    int M, int N, int K, int gOff, int atomicD,
    long sAz, long sBz, long sDz,
    const int* __restrict__ counts, const int* __restrict__ rowidx,
    const int* __restrict__ cIdx, const float* __restrict__ cW) {
    extern __shared__ __align__(128) char smem[];
    int z = blockIdx.z;
    if (counts) M = counts[z];
    int m0 = blockIdx.y * 128;
    if (m0 >= M) return;
    int n0 = blockIdx.x * 128;
    A += (size_t)z * sAz; B += (size_t)z * sBz;

    int tid = threadIdx.x, wid = tid >> 5, lane = tid & 31;
    int wm = (wid & 1) * 64;
    uint32_t sbase = smem_u32(smem);

    const float* pA;
    int ar[4];
    if (rowidx) {
        const int* ridx = rowidx + (size_t)z * CAP + m0;
        pA = A;
        #pragma unroll
        for (int i = 0; i < 4; i++) ar[i] = ridx[(tid >> 3) + 32 * i];
    } else {
        pA = A + (size_t)m0 * K;
        #pragma unroll
        for (int i = 0; i < 4; i++) ar[i] = (tid >> 3) + 32 * i;
    }

    float acc[4][4][4];
    #pragma unroll
    for (int i = 0; i < 4; i++)
        #pragma unroll
        for (int j = 0; j < 4; j++)
            #pragma unroll
            for (int r = 0; r < 4; r++) acc[i][j][r] = 0.f;

    const int nk = K >> 5;
    issue_stage(sbase,             pA, B, K, N, 0,  n0, gOff, tid, ar); CP_COMMIT();
    issue_stage(sbase + STG_BYTES, pA, B, K, N, 32, n0, gOff, tid, ar); CP_COMMIT();

    uint32_t aoff = (uint32_t)((wm + (lane & 15)) * ROWB + ((lane >> 4) & 1) * 16);
    int sbg[4];
    if (gOff) {
        int wny = (wid >> 1) * 16;
        #pragma unroll
        for (int g = 0; g < 4; g++) sbg[g] = ((g & 2) ? 64 : 0) + wny + (g & 1) * 8;
    } else {
        int wn = (wid >> 1) * 32;
        #pragma unroll
        for (int g = 0; g < 4; g++) sbg[g] = wn + g * 8;
    }
    uint32_t brow0 = (uint32_t)((lane & 3) * BROW);
    uint32_t blane = (uint32_t)((lane >> 2) * 4);

    int stg = 0;
    for (int kc = 0; kc < nk; kc++) {
        CP_WAIT1();
        __syncthreads();
        if (kc + 2 < nk) {
            int nx = stg + 2; if (nx >= 3) nx -= 3;
            issue_stage(sbase + nx * STG_BYTES, pA, B, K, N, (kc + 2) * 32, n0, gOff, tid, ar);
        }
        CP_COMMIT();

        uint32_t sA = sbase + stg * STG_BYTES;
        uint32_t sB = sA + A_BYTES + brow0 + blane;
        #pragma unroll
        for (int s = 0; s < 4; s++) {
            uint32_t a[4][4];
            #pragma unroll
            for (int mi = 0; mi < 4; mi++)
                ldm_x4(a[mi], sA + aoff + (uint32_t)(mi * 16 * ROWB + s * 32));
            #pragma unroll
            for (int g = 0; g < 4; g++) {
                uint32_t b[2];
                uint32_t ba = sB + (uint32_t)(s * 8 * BROW + sbg[g] * 4);
                LDS32(b[0], ba);
                LDS32(b[1], ba + 4 * BROW);
                b[0] = cvt_tf32_u(b[0]);
                b[1] = cvt_tf32_u(b[1]);
                #pragma unroll
                for (int mi = 0; mi < 4; mi++)
                    mma_tf32(acc[mi][g], a[mi], b);
            }
        }
        if (++stg == 3) stg = 0;
    }

    int r0 = lane >> 2, c0 = (lane & 3) * 2;
    if (H) {
        int halfN = N >> 1;
        int hb = n0 >> 1;
        int wny = (wid >> 1) * 16;
        H += (size_t)z * sDz;
        #pragma unroll
        for (int mi = 0; mi < 4; mi++) {
            #pragma unroll
            for (int g = 0; g < 2; g++) {
                int row = m0 + wm + mi * 16 + r0;
                int hcol = hb + wny + g * 8 + c0;
                float y0 = acc[mi][g][0], gg0 = acc[mi][g + 2][0];
                float y1 = acc[mi][g][1], gg1 = acc[mi][g + 2][1];
                float y2 = acc[mi][g][2], gg2 = acc[mi][g + 2][2];
                float y3 = acc[mi][g][3], gg3 = acc[mi][g + 2][3];
                H[(size_t)row * halfN + hcol]           = to_tf32(y0 * gg0 / (1.f + __expf(-gg0)));
                H[(size_t)row * halfN + hcol + 1]       = to_tf32(y1 * gg1 / (1.f + __expf(-gg1)));
                H[(size_t)(row + 8) * halfN + hcol]     = to_tf32(y2 * gg2 / (1.f + __expf(-gg2)));
                H[(size_t)(row + 8) * halfN + hcol + 1] = to_tf32(y3 * gg3 / (1.f + __expf(-gg3)));
            }
        }
    } else if (cIdx) {
        const int* ridx = cIdx + (size_t)z * CAP;
        const float* wv = cW + (size_t)z * CAP;
        int wn = (wid >> 1) * 32;
        #pragma unroll
        for (int mi = 0; mi < 4; mi++) {
            int row = m0 + wm + mi * 16 + r0;
            #pragma unroll
            for (int h = 0; h < 2; h++) {
                int rr = row + h * 8;
                if (rr < M) {
                    int tt = ridx[rr];
                    float w = wv[rr];
                    float* O = D + (size_t)tt * CDIM;
                    #pragma unroll
                    for (int g = 0; g < 4; g++) {
                        int col = n0 + wn + g * 8 + c0;
                        atomicAdd(O + col,     w * acc[mi][g][h * 2]);
                        atomicAdd(O + col + 1, w * acc[mi][g][h * 2 + 1]);
                    }
                }
            }
        }
    } else if (atomicD) {
        int wn = (wid >> 1) * 32;
        #pragma unroll
        for (int mi = 0; mi < 4; mi++) {
            #pragma unroll
            for (int g = 0; g < 4; g++) {
                int row = m0 + wm + mi * 16 + r0;
                int col = n0 + wn + g * 8 + c0;
                atomicAdd(D + (size_t)row * N + col,     acc[mi][g][0]);
                atomicAdd(D + (size_t)row * N + col + 1, acc[mi][g][1]);
                atomicAdd(D + (size_t)(row + 8) * N + col,     acc[mi][g][2]);
                atomicAdd(D + (size_t)(row + 8) * N + col + 1, acc[mi][g][3]);
            }
        }
    } else {
        D += (size_t)z * sDz;
        int wn = (wid >> 1) * 32;
        #pragma unroll
        for (int mi = 0; mi < 4; mi++) {
            #pragma unroll
            for (int g = 0; g < 4; g++) {
                int row = m0 + wm + mi * 16 + r0;
                int col = n0 + wn + g * 8 + c0;
                *(float2*)(D + (size_t)row * N + col) = make_float2(acc[mi][g][0], acc[mi][g][1]);
                *(float2*)(D + (size_t)(row + 8) * N + col) = make_float2(acc[mi][g][2], acc[mi][g][3]);
            }
        }
    }
}

// ---------------- launch (3-stream pipelined DAG; record-before-wait order) ----------------
extern "C" void kernel_launch(void* const* d_in, const int* in_sizes, int n_in,
                              void* d_out, int out_size) {
    const float* x       = (const float*)d_in[0];
    const float* rw      = (const float*)d_in[1];
    const float* bias    = (const float*)d_in[2];
    const float* sup_w   = (const float*)d_in[3];
    const float* sdown_w = (const float*)d_in[4];
    const float* eup_w   = (const float*)d_in[5];
    const float* edown_w = (const float*)d_in[6];
    float* out = (float*)d_out;
    (void)in_sizes; (void)n_in; (void)out_size;

    float *xr, *sh, *eh, *swts;
    int *counts, *rowidx;
    cudaGetSymbolAddress((void**)&xr, g_xr);
    cudaGetSymbolAddress((void**)&sh, g_sh);
    cudaGetSymbolAddress((void**)&eh, g_eh);
    cudaGetSymbolAddress((void**)&swts, g_swts);
    cudaGetSymbolAddress((void**)&counts, g_counts);
    cudaGetSymbolAddress((void**)&rowidx, g_rowidx);

    cudaFuncSetAttribute(gemm_kernel, cudaFuncAttributeMaxDynamicSharedMemorySize, 3 * STG_BYTES);
    const int gsmem = 3 * STG_BYTES;

    static cudaStream_t s1 = nullptr, s2 = nullptr;
    static cudaEvent_t evFork = nullptr, evXr = nullptr, evR = nullptr, evZ = nullptr,
                       evJ1 = nullptr, evJ2 = nullptr;
    if (!s1) {
        cudaStreamCreateWithFlags(&s1, cudaStreamNonBlocking);
        cudaStreamCreateWithFlags(&s2, cudaStreamNonBlocking);
        cudaEventCreateWithFlags(&evFork, cudaEventDisableTiming);
        cudaEventCreateWithFlags(&evXr, cudaEventDisableTiming);
        cudaEventCreateWithFlags(&evR, cudaEventDisableTiming);
        cudaEventCreateWithFlags(&evZ, cudaEventDisableTiming);
        cudaEventCreateWithFlags(&evJ1, cudaEventDisableTiming);
        cudaEventCreateWithFlags(&evJ2, cudaEventDisableTiming);
    }

    // half-1 pointer offsets (experts 32..63)
    const float* eup_w1   = eup_w   + (size_t)EHALF * CDIM * (2 * HE);
    const float* edown_w1 = edown_w + (size_t)EHALF * HE * CDIM;
    float* eh1 = eh + (size_t)EHALF * CAP * HE;

    // ---- fork ----
    cudaEventRecord(evFork, 0);
    cudaStreamWaitEvent(s1, evFork, 0);
    cudaStreamWaitEvent(s2, evFork, 0);

    // s2: zero out accumulator FIRST; record evZ before anyone waits on it
    zero_out_kernel<<<NTOK * CDIM / 4 / 256, 256, 0, s2>>>(out);
    cudaEventRecord(evZ, s2);

    // s1: xr; record evXr before anyone waits on it
    xr_kernel<<<NTOK * CDIM / 4 / 256, 256, 0, s1>>>(x, xr);
    cudaEventRecord(evXr, s1);

    // main: counts + router; record evR
    zero_counts_kernel<<<1, 64>>>(counts);
    router_kernel<<<NTOK, 256>>>(x, rw, bias, counts, rowidx, swts);
    cudaEventRecord(evR, 0);

    // s1: shared-up -> (wait zero) shared-down (atomic into out)
    gemm_kernel<<<dim3(2 * HS / 128, NTOK / 128, 1), 256, gsmem, s1>>>(
        xr, sup_w, nullptr, sh, NTOK, 2 * HS, CDIM, HS, 0, 0, 0, 0,
        nullptr, nullptr, nullptr, nullptr);
    cudaStreamWaitEvent(s1, evZ, 0);
    gemm_kernel<<<dim3(CDIM / 128, NTOK / 128, 1), 256, gsmem, s1>>>(
        sh, sdown_w, out, nullptr, NTOK, CDIM, HS, 0, 1, 0, 0, 0,
        nullptr, nullptr, nullptr, nullptr);

    // s2: (wait xr + router) expert half-1 up -> down (zero already ordered on s2)
    cudaStreamWaitEvent(s2, evXr, 0);
    cudaStreamWaitEvent(s2, evR, 0);
    gemm_kernel<<<dim3(2 * HE / 128, CAP / 128, EHALF), 256, gsmem, s2>>>(
        xr, eup_w1, nullptr, eh1, CAP, 2 * HE, CDIM, HE, 0,
        0, (long)CDIM * (2 * HE), (long)CAP * HE,
        counts + EHALF, rowidx + (size_t)EHALF * CAP, nullptr, nullptr);
    gemm_kernel<<<dim3(CDIM / 128, CAP / 128, EHALF), 256, gsmem, s2>>>(
        eh1, edown_w1, out, nullptr, CAP, CDIM, HE, 0, 0,
        (long)CAP * HE, (long)HE * CDIM, 0,
        counts + EHALF, nullptr, rowidx + (size_t)EHALF * CAP, swts + (size_t)EHALF * CAP);

    // main: (wait xr) expert half-0 up -> (wait zero) down
    cudaStreamWaitEvent(0, evXr, 0);
    gemm_kernel<<<dim3(2 * HE / 128, CAP / 128, EHALF), 256, gsmem>>>(
        xr, eup_w, nullptr, eh, CAP, 2 * HE, CDIM, HE, 0,
        0, (long)CDIM * (2 * HE), (long)CAP * HE, counts, rowidx, nullptr, nullptr);
    cudaStreamWaitEvent(0, evZ, 0);
    gemm_kernel<<<dim3(CDIM / 128, CAP / 128, EHALF), 256, gsmem>>>(
        eh, edown_w, out, nullptr, CAP, CDIM, HE, 0, 0,
        (long)CAP * HE, (long)HE * CDIM, 0, counts, nullptr, rowidx, swts);

    // ---- join ----
    cudaEventRecord(evJ1, s1);
    cudaStreamWaitEvent(0, evJ1, 0);
    cudaEventRecord(evJ2, s2);
    cudaStreamWaitEvent(0, evJ2, 0);
}